// round 1
// baseline (speedup 1.0000x reference)
#include <cuda_runtime.h>
#include <cuda_bf16.h>

#define ALPHA 0.2f
#define KDIM 4096
#define NDIM 1024

// Scratch (allocation-free rule: __device__ globals)
__device__ float g_s1[KDIM];
__device__ float g_s2[KDIM];
__device__ float g_m[KDIM];    // per-row max of lrelu scores
__device__ float g_rz[KDIM];   // 1 / softmax denominator
__device__ float g_s2max;

__device__ __forceinline__ float lrelu(float t) {
    return (t > 0.f) ? t : ALPHA * t;
}

// ---------------------------------------------------------------------------
// K1: s1[i] = x[i,:] . w1 ; s2[i] = x[i,:] . w2     (one block per row)
// ---------------------------------------------------------------------------
__global__ void k_scores(const float* __restrict__ x, const float* __restrict__ w) {
    int i = blockIdx.x;
    int t = threadIdx.x;  // 256 threads, 4 floats each = 1024
    const float4* xr = reinterpret_cast<const float4*>(x + (size_t)i * NDIM);
    const float4* w1 = reinterpret_cast<const float4*>(w);
    const float4* w2 = reinterpret_cast<const float4*>(w + NDIM);
    float4 xv = xr[t];
    float4 a  = w1[t];
    float4 b  = w2[t];
    float d1 = xv.x * a.x + xv.y * a.y + xv.z * a.z + xv.w * a.w;
    float d2 = xv.x * b.x + xv.y * b.y + xv.z * b.z + xv.w * b.w;
    #pragma unroll
    for (int o = 16; o > 0; o >>= 1) {
        d1 += __shfl_down_sync(0xffffffffu, d1, o);
        d2 += __shfl_down_sync(0xffffffffu, d2, o);
    }
    __shared__ float sm1[8], sm2[8];
    if ((t & 31) == 0) { sm1[t >> 5] = d1; sm2[t >> 5] = d2; }
    __syncthreads();
    if (t == 0) {
        float s1 = 0.f, s2 = 0.f;
        #pragma unroll
        for (int wq = 0; wq < 8; wq++) { s1 += sm1[wq]; s2 += sm2[wq]; }
        g_s1[i] = s1;
        g_s2[i] = s2;
    }
}

// ---------------------------------------------------------------------------
// K2: g_s2max = max_j s2[j]   (single block)
// ---------------------------------------------------------------------------
__global__ void k_max() {
    int t = threadIdx.x;  // 256
    float m = -1e30f;
    for (int j = t; j < KDIM; j += 256) m = fmaxf(m, g_s2[j]);
    #pragma unroll
    for (int o = 16; o > 0; o >>= 1) m = fmaxf(m, __shfl_down_sync(0xffffffffu, m, o));
    __shared__ float sm[8];
    if ((t & 31) == 0) sm[t >> 5] = m;
    __syncthreads();
    if (t == 0) {
        float r = sm[0];
        #pragma unroll
        for (int wq = 1; wq < 8; wq++) r = fmaxf(r, sm[wq]);
        g_s2max = r;
    }
}

// ---------------------------------------------------------------------------
// K3: m[i] = lrelu(s1[i] + s2max) ; rz[i] = 1 / sum_j exp(lrelu(s1+s2[j]) - m)
// (one block per row; s2 staged in smem)
// ---------------------------------------------------------------------------
__global__ void k_z() {
    int i = blockIdx.x;
    int t = threadIdx.x;  // 256
    __shared__ float s2s[KDIM];  // 16 KB
    for (int j = t; j < KDIM; j += 256) s2s[j] = g_s2[j];
    __syncthreads();
    float s1 = g_s1[i];
    float m  = lrelu(s1 + g_s2max);
    float z = 0.f;
    for (int j = t; j < KDIM; j += 256)
        z += __expf(lrelu(s1 + s2s[j]) - m);
    #pragma unroll
    for (int o = 16; o > 0; o >>= 1) z += __shfl_down_sync(0xffffffffu, z, o);
    __shared__ float sm[8];
    if ((t & 31) == 0) sm[t >> 5] = z;
    __syncthreads();
    if (t == 0) {
        float s = 0.f;
        #pragma unroll
        for (int wq = 0; wq < 8; wq++) s += sm[wq];
        g_m[i]  = m;
        g_rz[i] = 1.f / s;
    }
}

// ---------------------------------------------------------------------------
// K4: h = (P .* rz_row) @ x  with P computed on the fly.
// Tiles: BM=64, BN=128, BK=32. 256 threads, each computes 4x8 outputs.
// ---------------------------------------------------------------------------
#define BM 64
#define BN 128
#define BK 32

__global__ __launch_bounds__(256) void k_gemm(const float* __restrict__ x,
                                              float* __restrict__ out) {
    __shared__ float As[BK][BM];   // P tile (k-major for GEMM)
    __shared__ float Bs[BK][BN];   // x tile
    __shared__ float s1s[BM], ms[BM], rzs[BM];

    int tid = threadIdx.x;
    int m0 = blockIdx.y * BM;
    int n0 = blockIdx.x * BN;

    if (tid < BM) {
        s1s[tid] = g_s1[m0 + tid];
        ms[tid]  = g_m[m0 + tid];
        rzs[tid] = g_rz[m0 + tid];
    }

    int trow = tid >> 4;   // 0..15  -> rows trow*4 .. +3
    int tcol = tid & 15;   // 0..15  -> cols tcol*8 .. +7

    float acc[4][8];
    #pragma unroll
    for (int r = 0; r < 4; r++)
        #pragma unroll
        for (int c = 0; c < 8; c++) acc[r][c] = 0.f;

    int brow = tid >> 5;          // 0..7, Bs row stager
    int bcol = (tid & 31) * 4;    // float4 column

    for (int j0 = 0; j0 < KDIM; j0 += BK) {
        __syncthreads();  // previous tile fully consumed

        // Stage x tile
        #pragma unroll
        for (int r = brow; r < BK; r += 8) {
            *reinterpret_cast<float4*>(&Bs[r][bcol]) =
                *reinterpret_cast<const float4*>(&x[(size_t)(j0 + r) * NDIM + n0 + bcol]);
        }
        // Compute P tile on the fly (8 elems per thread)
        #pragma unroll
        for (int e = 0; e < (BK * BM) / 256; e++) {
            int idx = tid + e * 256;
            int k = idx >> 6;       // BK index
            int i = idx & 63;       // BM index
            float tsum = s1s[i] + __ldg(&g_s2[j0 + k]);
            float l = (tsum > 0.f) ? tsum : ALPHA * tsum;
            As[k][i] = __expf(l - ms[i]);
        }
        __syncthreads();

        #pragma unroll
        for (int k = 0; k < BK; k++) {
            float4 a  = *reinterpret_cast<const float4*>(&As[k][trow * 4]);
            float4 b0 = *reinterpret_cast<const float4*>(&Bs[k][tcol * 8]);
            float4 b1 = *reinterpret_cast<const float4*>(&Bs[k][tcol * 8 + 4]);
            float av[4] = {a.x, a.y, a.z, a.w};
            float bv[8] = {b0.x, b0.y, b0.z, b0.w, b1.x, b1.y, b1.z, b1.w};
            #pragma unroll
            for (int r = 0; r < 4; r++)
                #pragma unroll
                for (int c = 0; c < 8; c++)
                    acc[r][c] = fmaf(av[r], bv[c], acc[r][c]);
        }
    }

    // Epilogue: scale by 1/Z and store
    #pragma unroll
    for (int r = 0; r < 4; r++) {
        int row = m0 + trow * 4 + r;
        float rz = rzs[trow * 4 + r];
        float4 o0 = make_float4(acc[r][0] * rz, acc[r][1] * rz, acc[r][2] * rz, acc[r][3] * rz);
        float4 o1 = make_float4(acc[r][4] * rz, acc[r][5] * rz, acc[r][6] * rz, acc[r][7] * rz);
        float* dst = out + (size_t)row * NDIM + n0 + tcol * 8;
        *reinterpret_cast<float4*>(dst)     = o0;
        *reinterpret_cast<float4*>(dst + 4) = o1;
    }
}

// ---------------------------------------------------------------------------
extern "C" void kernel_launch(void* const* d_in, const int* in_sizes, int n_in,
                              void* d_out, int out_size) {
    const float* x = (const float*)d_in[0];   // (4096, 1024) fp32
    const float* w = (const float*)d_in[1];   // (2048, 1) fp32
    float* out = (float*)d_out;               // (4096, 1024) fp32

    k_scores<<<KDIM, 256>>>(x, w);
    k_max<<<1, 256>>>();
    k_z<<<KDIM, 256>>>();
    dim3 grid(NDIM / BN, KDIM / BM);  // (8, 64)
    k_gemm<<<grid, 256>>>(x, out);
}

// round 3
// speedup vs baseline: 4.5785x; 4.5785x over previous
#include <cuda_runtime.h>
#include <cuda_bf16.h>
#include <cstdint>

#define ALPHA 0.2f
#define KDIM 4096
#define NDIM 1024

// ---------------- scratch (__device__ globals; no allocs allowed) ----------
__device__ float g_s1[KDIM];
__device__ float g_s2[KDIM];
__device__ float g_eb[KDIM];    // exp(s2_j)
__device__ float g_ed[KDIM];    // exp(ALPHA*s2_j)
__device__ float g_ap[KDIM];    // exp(s1_i - m_i) / Z_i
__device__ float g_cp[KDIM];    // exp(ALPHA*s1_i - m_i) / Z_i
__device__ float g_s2max;
__device__ float g_P[(size_t)KDIM * KDIM];   // normalized P, tf32-rounded (64 MB)

__device__ __forceinline__ float lrelu(float t) { return (t > 0.f) ? t : ALPHA * t; }

__device__ __forceinline__ uint32_t f2tf32(float v) {
    uint32_t r;
    asm("cvt.rna.tf32.f32 %0, %1;" : "=r"(r) : "f"(v));
    return r;
}

__device__ __forceinline__ uint32_t smem_u32(const void* p) {
    uint32_t a;
    asm("{ .reg .u64 t; cvta.to.shared.u64 t, %1; cvt.u32.u64 %0, t; }" : "=r"(a) : "l"(p));
    return a;
}

// ---------------------------------------------------------------------------
// K1: s1[i] = x[i,:].w1 ; s2[i] = x[i,:].w2
// ---------------------------------------------------------------------------
__global__ void k_scores(const float* __restrict__ x, const float* __restrict__ w) {
    int i = blockIdx.x;
    int t = threadIdx.x;
    const float4* xr = reinterpret_cast<const float4*>(x + (size_t)i * NDIM);
    const float4* w1 = reinterpret_cast<const float4*>(w);
    const float4* w2 = reinterpret_cast<const float4*>(w + NDIM);
    float4 xv = xr[t];
    float4 a = w1[t];
    float4 b = w2[t];
    float d1 = xv.x * a.x + xv.y * a.y + xv.z * a.z + xv.w * a.w;
    float d2 = xv.x * b.x + xv.y * b.y + xv.z * b.z + xv.w * b.w;
    #pragma unroll
    for (int o = 16; o > 0; o >>= 1) {
        d1 += __shfl_down_sync(0xffffffffu, d1, o);
        d2 += __shfl_down_sync(0xffffffffu, d2, o);
    }
    __shared__ float sm1[8], sm2[8];
    if ((t & 31) == 0) { sm1[t >> 5] = d1; sm2[t >> 5] = d2; }
    __syncthreads();
    if (t == 0) {
        float s1 = 0.f, s2 = 0.f;
        #pragma unroll
        for (int q = 0; q < 8; q++) { s1 += sm1[q]; s2 += sm2[q]; }
        g_s1[i] = s1;
        g_s2[i] = s2;
    }
}

// K2: global max of s2
__global__ void k_max() {
    int t = threadIdx.x;
    float m = -1e30f;
    for (int j = t; j < KDIM; j += 256) m = fmaxf(m, g_s2[j]);
    #pragma unroll
    for (int o = 16; o > 0; o >>= 1) m = fmaxf(m, __shfl_down_sync(0xffffffffu, m, o));
    __shared__ float sm[8];
    if ((t & 31) == 0) sm[t >> 5] = m;
    __syncthreads();
    if (t == 0) {
        float r = sm[0];
        #pragma unroll
        for (int q = 1; q < 8; q++) r = fmaxf(r, sm[q]);
        g_s2max = r;
    }
}

// K3: factored exp terms (16K exps total)
__global__ void k_factors() {
    int i = blockIdx.x * 256 + threadIdx.x;
    if (i >= KDIM) return;
    float s1 = g_s1[i], s2 = g_s2[i];
    float m = lrelu(s1 + g_s2max);
    g_ap[i] = __expf(s1 - m);
    g_cp[i] = __expf(ALPHA * s1 - m);
    g_eb[i] = __expf(s2);
    g_ed[i] = __expf(ALPHA * s2);
}

// K4: Z_i via factored select-sum; fold 1/Z into ap/cp
__global__ void k_z() {
    int i = blockIdx.x;
    int t = threadIdx.x;  // 256
    float s1 = g_s1[i];
    float a = g_ap[i], c = g_cp[i];
    float z = 0.f;
    for (int j = t * 4; j < KDIM; j += 1024) {
        float4 s2v = *reinterpret_cast<const float4*>(g_s2 + j);
        float4 bv = *reinterpret_cast<const float4*>(g_eb + j);
        float4 dv = *reinterpret_cast<const float4*>(g_ed + j);
        z += (s1 + s2v.x > 0.f) ? a * bv.x : c * dv.x;
        z += (s1 + s2v.y > 0.f) ? a * bv.y : c * dv.y;
        z += (s1 + s2v.z > 0.f) ? a * bv.z : c * dv.z;
        z += (s1 + s2v.w > 0.f) ? a * bv.w : c * dv.w;
    }
    #pragma unroll
    for (int o = 16; o > 0; o >>= 1) z += __shfl_down_sync(0xffffffffu, z, o);
    __shared__ float sm[8];
    if ((t & 31) == 0) sm[t >> 5] = z;
    __syncthreads();
    if (t == 0) {
        float s = 0.f;
        #pragma unroll
        for (int q = 0; q < 8; q++) s += sm[q];
        float rz = 1.f / s;
        g_ap[i] = a * rz;
        g_cp[i] = c * rz;
    }
}

// K5: materialize normalized P (tf32-rounded). One block per row i.
__global__ __launch_bounds__(256) void k_pgen() {
    int i = blockIdx.x;
    int t = threadIdx.x;
    float s1 = g_s1[i];
    float av = g_ap[i], cv = g_cp[i];
    float* Prow = g_P + (size_t)i * KDIM;
    #pragma unroll
    for (int q = 0; q < 4; q++) {
        int j = (q * 256 + t) * 4;
        float4 s2v = *reinterpret_cast<const float4*>(g_s2 + j);
        float4 bv = *reinterpret_cast<const float4*>(g_eb + j);
        float4 dv = *reinterpret_cast<const float4*>(g_ed + j);
        uint4 o;
        o.x = f2tf32((s1 + s2v.x > 0.f) ? av * bv.x : cv * dv.x);
        o.y = f2tf32((s1 + s2v.y > 0.f) ? av * bv.y : cv * dv.y);
        o.z = f2tf32((s1 + s2v.z > 0.f) ? av * bv.z : cv * dv.z);
        o.w = f2tf32((s1 + s2v.w > 0.f) ? av * bv.w : cv * dv.w);
        *reinterpret_cast<uint4*>(Prow + j) = o;
    }
}

// ---------------------------------------------------------------------------
// K6: GEMM h = P @ x via mma.sync tf32 (m16n8k8), cp.async 3-stage pipeline.
// BM=128, BN=128, BK=32. 256 threads = 8 warps (2 M x 4 N), warp tile 64x32.
// ---------------------------------------------------------------------------
#define BM 128
#define BN 128
#define BK 32
#define CHUNKS (KDIM / BK)
#define APAD 36     // floats per A row (BK + 4)
#define BPAD 136    // floats per B row (BN + 8)
#define ASF (BM * APAD)      // 4608 floats / stage
#define BSF (BK * BPAD)      // 4352 floats / stage
#define STAGEF (ASF + BSF)   // 8960 floats
#define NSTAGE 3
#define SMEM_BYTES (NSTAGE * STAGEF * 4)

__device__ __forceinline__ void cp_async16(uint32_t dst, const void* src) {
    asm volatile("cp.async.cg.shared.global [%0], [%1], 16;" :: "r"(dst), "l"(src));
}
__device__ __forceinline__ void cp_commit() {
    asm volatile("cp.async.commit_group;" ::: "memory");
}
__device__ __forceinline__ void cp_wait1() {
    asm volatile("cp.async.wait_group 1;" ::: "memory");
}

__device__ __forceinline__ void mma_tf32(float& d0, float& d1, float& d2, float& d3,
                                         uint32_t a0, uint32_t a1, uint32_t a2, uint32_t a3,
                                         uint32_t b0, uint32_t b1) {
    asm volatile(
        "mma.sync.aligned.m16n8k8.row.col.f32.tf32.tf32.f32 "
        "{%0,%1,%2,%3}, {%4,%5,%6,%7}, {%8,%9}, {%0,%1,%2,%3};"
        : "+f"(d0), "+f"(d1), "+f"(d2), "+f"(d3)
        : "r"(a0), "r"(a1), "r"(a2), "r"(a3), "r"(b0), "r"(b1));
}

__global__ __launch_bounds__(256, 1) void k_gemm(const float* __restrict__ x,
                                                 float* __restrict__ out) {
    extern __shared__ float sm[];
    int tid = threadIdx.x;
    int wid = tid >> 5;
    int lane = tid & 31;
    int wm = wid >> 2;        // 0..1
    int wn = wid & 3;         // 0..3
    int gr = lane >> 2;       // 0..7
    int gc = lane & 3;        // 0..3
    int m0 = blockIdx.y * BM;
    int n0 = blockIdx.x * BN;

    uint32_t smb = smem_u32(sm);

    float acc[4][4][4];
    #pragma unroll
    for (int mf = 0; mf < 4; mf++)
        #pragma unroll
        for (int nf = 0; nf < 4; nf++)
            #pragma unroll
            for (int r = 0; r < 4; r++) acc[mf][nf][r] = 0.f;

    // per-thread load indices
    // A: 4 float4 each; flat f = q*256 + tid; row m = f>>3, k4 = (f&7)*4
    // B: 4 float4 each; flat f = q*256 + tid; row k = f>>5, n4 = (f&31)*4
    auto load_stage = [&](int c, int s) {
        int j0 = c * BK;
        uint32_t abase = smb + (uint32_t)(s * STAGEF) * 4u;
        uint32_t bbase = abase + (uint32_t)ASF * 4u;
        #pragma unroll
        for (int q = 0; q < 4; q++) {
            int f = q * 256 + tid;
            int m = f >> 3;
            int k4 = (f & 7) * 4;
            cp_async16(abase + (uint32_t)(m * APAD + k4) * 4u,
                       g_P + (size_t)(m0 + m) * KDIM + j0 + k4);
        }
        #pragma unroll
        for (int q = 0; q < 4; q++) {
            int f = q * 256 + tid;
            int k = f >> 5;
            int n4 = (f & 31) * 4;
            cp_async16(bbase + (uint32_t)(k * BPAD + n4) * 4u,
                       x + (size_t)(j0 + k) * NDIM + n0 + n4);
        }
    };

    load_stage(0, 0); cp_commit();
    load_stage(1, 1); cp_commit();

    for (int c = 0; c < CHUNKS; c++) {
        cp_wait1();
        __syncthreads();

        if (c + 2 < CHUNKS) load_stage(c + 2, (c + 2) % NSTAGE);
        cp_commit();

        const float* As = sm + (size_t)(c % NSTAGE) * STAGEF;
        const float* Bs = As + ASF;
        const uint32_t* Au = reinterpret_cast<const uint32_t*>(As);
        const uint32_t* Bu = reinterpret_cast<const uint32_t*>(Bs);

        #pragma unroll
        for (int kf = 0; kf < 4; kf++) {
            uint32_t a[4][4];
            uint32_t b[4][2];
            #pragma unroll
            for (int mf = 0; mf < 4; mf++) {
                int row = wm * 64 + mf * 16 + gr;
                int col = kf * 8 + gc;
                a[mf][0] = Au[row * APAD + col];
                a[mf][1] = Au[(row + 8) * APAD + col];
                a[mf][2] = Au[row * APAD + col + 4];
                a[mf][3] = Au[(row + 8) * APAD + col + 4];
            }
            #pragma unroll
            for (int nf = 0; nf < 4; nf++) {
                int brow = kf * 8 + gc;
                int bcol = wn * 32 + nf * 8 + gr;
                b[nf][0] = Bu[brow * BPAD + bcol];
                b[nf][1] = Bu[(brow + 4) * BPAD + bcol];
            }
            #pragma unroll
            for (int mf = 0; mf < 4; mf++)
                #pragma unroll
                for (int nf = 0; nf < 4; nf++)
                    mma_tf32(acc[mf][nf][0], acc[mf][nf][1], acc[mf][nf][2], acc[mf][nf][3],
                             a[mf][0], a[mf][1], a[mf][2], a[mf][3],
                             b[nf][0], b[nf][1]);
        }
        __syncthreads();
    }

    // Epilogue: direct stores (P pre-normalized; no scaling)
    #pragma unroll
    for (int mf = 0; mf < 4; mf++) {
        int row = m0 + wm * 64 + mf * 16 + gr;
        #pragma unroll
        for (int nf = 0; nf < 4; nf++) {
            int col = n0 + wn * 32 + nf * 8 + 2 * gc;
            *reinterpret_cast<float2*>(out + (size_t)row * NDIM + col) =
                make_float2(acc[mf][nf][0], acc[mf][nf][1]);
            *reinterpret_cast<float2*>(out + (size_t)(row + 8) * NDIM + col) =
                make_float2(acc[mf][nf][2], acc[mf][nf][3]);
        }
    }
}

// ---------------------------------------------------------------------------
extern "C" void kernel_launch(void* const* d_in, const int* in_sizes, int n_in,
                              void* d_out, int out_size) {
    const float* x = (const float*)d_in[0];   // (4096, 1024) fp32
    const float* w = (const float*)d_in[1];   // (2048, 1) fp32
    float* out = (float*)d_out;               // (4096, 1024) fp32

    k_scores<<<KDIM, 256>>>(x, w);
    k_max<<<1, 256>>>();
    k_factors<<<KDIM / 256, 256>>>();
    k_z<<<KDIM, 256>>>();
    k_pgen<<<KDIM, 256>>>();

    cudaFuncSetAttribute(k_gemm, cudaFuncAttributeMaxDynamicSharedMemorySize, SMEM_BYTES);
    dim3 grid(NDIM / BN, KDIM / BM);  // (8, 32) = 256 CTAs
    k_gemm<<<grid, 256, SMEM_BYTES>>>(x, out);
}

// round 4
// speedup vs baseline: 25.2688x; 5.5190x over previous
#include <cuda_runtime.h>
#include <cuda_bf16.h>
#include <cstdint>

#define ALPHA 0.2f
#define KDIM 4096
#define NDIM 1024
#define CH 32
#define NCHUNK (KDIM / CH)   // 128

// ---------------- scratch (__device__ globals; no allocs allowed) ----------
__device__ float g_s1[KDIM], g_s2[KDIM];
__device__ float g_ea[KDIM], g_ec[KDIM];        // exp(s1), exp(0.2 s1)
__device__ float g_eb[KDIM], g_ed[KDIM];        // exp(s2), exp(0.2 s2)
__device__ float g_sorted[KDIM];                // s2 ascending
__device__ int   g_sigma[KDIM];                 // sorted rank -> original index
__device__ float g_ebS[KDIM], g_edS[KDIM];      // eb/ed in sorted order
__device__ float g_sb[KDIM + 1], g_sd[KDIM + 1];// scalar global suffix sums
__device__ float g_sufB[(size_t)KDIM * NDIM];   // chunk-local vector suffix sums (16MB)
__device__ float g_sufD[(size_t)KDIM * NDIM];   // 16MB
__device__ float g_carB[NCHUNK * NDIM];         // chunk carry (exclusive suffix of chunk totals)
__device__ float g_carD[NCHUNK * NDIM];

// ---------------------------------------------------------------------------
// K1: s1[i] = x[i,:].w1 ; s2[i] = x[i,:].w2 ; plus the 4 exp factors
// ---------------------------------------------------------------------------
__global__ void k_scores(const float* __restrict__ x, const float* __restrict__ w) {
    int i = blockIdx.x;
    int t = threadIdx.x;  // 256 threads * float4 = 1024
    const float4* xr = reinterpret_cast<const float4*>(x + (size_t)i * NDIM);
    const float4* w1 = reinterpret_cast<const float4*>(w);
    const float4* w2 = reinterpret_cast<const float4*>(w + NDIM);
    float4 xv = xr[t];
    float4 a = w1[t];
    float4 b = w2[t];
    float d1 = xv.x * a.x + xv.y * a.y + xv.z * a.z + xv.w * a.w;
    float d2 = xv.x * b.x + xv.y * b.y + xv.z * b.z + xv.w * b.w;
    #pragma unroll
    for (int o = 16; o > 0; o >>= 1) {
        d1 += __shfl_down_sync(0xffffffffu, d1, o);
        d2 += __shfl_down_sync(0xffffffffu, d2, o);
    }
    __shared__ float sm1[8], sm2[8];
    if ((t & 31) == 0) { sm1[t >> 5] = d1; sm2[t >> 5] = d2; }
    __syncthreads();
    if (t == 0) {
        float s1 = 0.f, s2 = 0.f;
        #pragma unroll
        for (int q = 0; q < 8; q++) { s1 += sm1[q]; s2 += sm2[q]; }
        g_s1[i] = s1;
        g_s2[i] = s2;
        g_ea[i] = __expf(s1);
        g_ec[i] = __expf(ALPHA * s1);
        g_eb[i] = __expf(s2);
        g_ed[i] = __expf(ALPHA * s2);
    }
}

// ---------------------------------------------------------------------------
// K2: exact rank of each s2 (ties broken by index) -> sorted arrays (scatter)
// ---------------------------------------------------------------------------
__global__ void k_rank() {
    int i = blockIdx.x;
    int t = threadIdx.x;  // 256
    float v = g_s2[i];
    int cnt = 0;
    #pragma unroll 4
    for (int j = t; j < KDIM; j += 256) {
        float u = g_s2[j];
        cnt += (u < v) || (u == v && j < i);
    }
    #pragma unroll
    for (int o = 16; o > 0; o >>= 1) cnt += __shfl_down_sync(0xffffffffu, cnt, o);
    __shared__ int sm[8];
    if ((t & 31) == 0) sm[t >> 5] = cnt;
    __syncthreads();
    if (t == 0) {
        int r = 0;
        #pragma unroll
        for (int q = 0; q < 8; q++) r += sm[q];
        g_sorted[r] = v;
        g_sigma[r] = i;
        g_ebS[r] = g_eb[i];
        g_edS[r] = g_ed[i];
    }
}

// ---------------------------------------------------------------------------
// K3: scalar global suffix sums of ebS and edS (one block, 1024 threads)
// ---------------------------------------------------------------------------
__global__ void k_sscan() {
    __shared__ float p[1024];
    int t = threadIdx.x;
    #pragma unroll
    for (int pass = 0; pass < 2; pass++) {
        const float* src = pass ? g_edS : g_ebS;
        float* dst = pass ? g_sd : g_sb;
        float e0 = src[4 * t], e1 = src[4 * t + 1], e2 = src[4 * t + 2], e3 = src[4 * t + 3];
        float part = e0 + e1 + e2 + e3;
        float v = part;
        p[t] = v;
        __syncthreads();
        #pragma unroll
        for (int off = 1; off < 1024; off <<= 1) {
            float add = (t + off < 1024) ? p[t + off] : 0.f;
            __syncthreads();
            v += add;
            p[t] = v;
            __syncthreads();
        }
        float excl = (t < 1023) ? p[t + 1] : 0.f;
        float s3 = e3 + excl;
        float s2v = e2 + s3;
        float s1v = e1 + s2v;
        float s0 = e0 + s1v;
        dst[4 * t]     = s0;
        dst[4 * t + 1] = s1v;
        dst[4 * t + 2] = s2v;
        dst[4 * t + 3] = s3;
        if (t == 0) dst[KDIM] = 0.f;
        __syncthreads();
    }
}

// ---------------------------------------------------------------------------
// K4: chunk-local vector suffix sums. Block = one chunk of CH=32 sorted rows,
// full 1024 columns (256 threads x float4). Rows processed descending with
// one-ahead prefetch of the gathered x row.
// ---------------------------------------------------------------------------
__global__ __launch_bounds__(256) void k_scan(const float* __restrict__ x) {
    int c = blockIdx.x;
    int tid = threadIdx.x;
    int col = tid * 4;
    __shared__ int ssig[CH];
    __shared__ float scb[CH], scd[CH];
    if (tid < CH) {
        int k = c * CH + tid;
        ssig[tid] = g_sigma[k];
        scb[tid] = g_ebS[k];
        scd[tid] = g_edS[k];
    }
    __syncthreads();

    float4 aB = make_float4(0.f, 0.f, 0.f, 0.f);
    float4 aD = make_float4(0.f, 0.f, 0.f, 0.f);

    float4 y = *reinterpret_cast<const float4*>(x + (size_t)ssig[CH - 1] * NDIM + col);
    #pragma unroll 4
    for (int r = CH - 1; r >= 0; r--) {
        float4 ynext = (r > 0)
            ? *reinterpret_cast<const float4*>(x + (size_t)ssig[r - 1] * NDIM + col)
            : y;
        float cb = scb[r], cd = scd[r];
        aB.x = fmaf(cb, y.x, aB.x); aB.y = fmaf(cb, y.y, aB.y);
        aB.z = fmaf(cb, y.z, aB.z); aB.w = fmaf(cb, y.w, aB.w);
        aD.x = fmaf(cd, y.x, aD.x); aD.y = fmaf(cd, y.y, aD.y);
        aD.z = fmaf(cd, y.z, aD.z); aD.w = fmaf(cd, y.w, aD.w);
        size_t ro = (size_t)(c * CH + r) * NDIM + col;
        *reinterpret_cast<float4*>(g_sufB + ro) = aB;
        *reinterpret_cast<float4*>(g_sufD + ro) = aD;
        y = ynext;
    }
}

// ---------------------------------------------------------------------------
// K5: chunk carries — exclusive suffix sums of chunk totals per column.
// 4 blocks x 256 threads; one column per thread; groups of 16 chunk totals
// preloaded for MLP.
// ---------------------------------------------------------------------------
__global__ __launch_bounds__(256) void k_carry() {
    int col = blockIdx.x * 256 + threadIdx.x;
    float aB = 0.f, aD = 0.f;
    for (int g = NCHUNK / 16 - 1; g >= 0; g--) {
        float tB[16], tD[16];
        #pragma unroll
        for (int q = 0; q < 16; q++) {
            size_t ro = (size_t)((g * 16 + q) * CH) * NDIM + col;
            tB[q] = g_sufB[ro];
            tD[q] = g_sufD[ro];
        }
        #pragma unroll
        for (int q = 15; q >= 0; q--) {
            int c = g * 16 + q;
            g_carB[c * NDIM + col] = aB;
            g_carD[c * NDIM + col] = aD;
            aB += tB[q];
            aD += tD[q];
        }
    }
}

// ---------------------------------------------------------------------------
// K6: output. Block = row i. Binary-search rank t_i of -s1_i, form
// h_i = (a_i*SufB(t) + c_i*(TotD - SufD(t))) / Z_i  with Z from scalar tables.
// ---------------------------------------------------------------------------
__global__ __launch_bounds__(256) void k_out(float* __restrict__ out) {
    int i = blockIdx.x;
    int tid = threadIdx.x;
    __shared__ int sT;
    __shared__ float sAZ, sCZ;
    if (tid == 0) {
        float key = -g_s1[i];
        int lo = 0, hi = KDIM;
        while (lo < hi) {
            int mid = (lo + hi) >> 1;
            if (g_sorted[mid] <= key) lo = mid + 1;
            else hi = mid;
        }
        int t = lo;
        float a = g_ea[i], c = g_ec[i];
        float Z = a * g_sb[t] + c * (g_sd[0] - g_sd[t]);
        float rZ = 1.f / Z;
        sT = t;
        sAZ = a * rZ;
        sCZ = c * rZ;
    }
    __syncthreads();
    int t = sT;
    float aZ = sAZ, cZ = sCZ;
    int col = tid * 4;

    bool in = (t < KDIM);
    int tt = in ? t : 0;
    int ch = tt / CH;
    size_t ro = (size_t)tt * NDIM + col;
    size_t co = (size_t)ch * NDIM + col;

    float4 sB = *reinterpret_cast<const float4*>(g_sufB + ro);
    float4 cB = *reinterpret_cast<const float4*>(g_carB + co);
    float4 sD = *reinterpret_cast<const float4*>(g_sufD + ro);
    float4 cD = *reinterpret_cast<const float4*>(g_carD + co);
    float4 sD0 = *reinterpret_cast<const float4*>(g_sufD + col);
    float4 cD0 = *reinterpret_cast<const float4*>(g_carD + col);

    float m = in ? 1.f : 0.f;  // t == KDIM: positive part empty, neg = full total
    float4 h;
    h.x = aZ * m * (sB.x + cB.x) + cZ * ((sD0.x + cD0.x) - m * (sD.x + cD.x));
    h.y = aZ * m * (sB.y + cB.y) + cZ * ((sD0.y + cD0.y) - m * (sD.y + cD.y));
    h.z = aZ * m * (sB.z + cB.z) + cZ * ((sD0.z + cD0.z) - m * (sD.z + cD.z));
    h.w = aZ * m * (sB.w + cB.w) + cZ * ((sD0.w + cD0.w) - m * (sD.w + cD.w));

    *reinterpret_cast<float4*>(out + (size_t)i * NDIM + col) = h;
}

// ---------------------------------------------------------------------------
extern "C" void kernel_launch(void* const* d_in, const int* in_sizes, int n_in,
                              void* d_out, int out_size) {
    const float* x = (const float*)d_in[0];   // (4096, 1024) fp32
    const float* w = (const float*)d_in[1];   // (2048, 1) fp32
    float* out = (float*)d_out;               // (4096, 1024) fp32

    k_scores<<<KDIM, 256>>>(x, w);
    k_rank<<<KDIM, 256>>>();
    k_sscan<<<1, 1024>>>();
    k_scan<<<NCHUNK, 256>>>(x);
    k_carry<<<4, 256>>>();
    k_out<<<KDIM, 256>>>(out);
}